// round 7
// baseline (speedup 1.0000x reference)
#include <cuda_runtime.h>

// Fused NeRF MLP forward, tf32 tensor-core (mma.sync.m16n8k8) with fp32 accum.
// 64 points per CTA, 256 threads (8 warps). Each warp: 32 rows x 64 cols
// (2x m16 groups, 8x n8 tiles) -> full accumulator in registers, single
// in-place activation buffer in smem.

#define NPTS 262144
#define TILE 64
#define BLK  256

#define HST   260   // activation smem stride  (260 % 32 == 4 -> conflict-free A frags)
#define XST   68    // xyz posenc stride
#define DST   36    // dir posenc stride
#define WST   264   // weight-chunk stride     (264 % 32 == 8 -> conflict-free B frags)
#define HIDST 132   // rgb hidden stride

#define SMEM_FLOATS (TILE*(HST + XST + DST + WST + HIDST) + TILE)
#define SMEM_BYTES  (SMEM_FLOATS * 4)

struct Params {
    const float* x;
    const float* w[8];
    const float* b[8];
    const float *wf, *bf, *ws, *bs, *wr1, *br1, *wr2, *br2;
    float* out;
};

__device__ __forceinline__ float tf32r(float v) {
    unsigned u;
    asm("cvt.rna.tf32.f32 %0, %1;" : "=r"(u) : "f"(v));
    return __uint_as_float(u);
}

__device__ __forceinline__ void mma8(float c[4], const unsigned a[4],
                                     unsigned b0, unsigned b1) {
    asm volatile(
        "mma.sync.aligned.m16n8k8.row.col.f32.tf32.tf32.f32 "
        "{%0,%1,%2,%3}, {%4,%5,%6,%7}, {%8,%9}, {%0,%1,%2,%3};\n"
        : "+f"(c[0]), "+f"(c[1]), "+f"(c[2]), "+f"(c[3])
        : "r"(a[0]), "r"(a[1]), "r"(a[2]), "r"(a[3]), "r"(b0), "r"(b1));
}

// Accumulate sA[64 x kpad] @ gW[k_real x (NT*32)] into acc.
// sA rows at sA[r*ast + k]; k in [k_real, kpad) treated as zero on both sides
// (caller guarantees A cols >= k_real are zeroed; W rows guarded here).
template<int NT>
__device__ __forceinline__ void gemm_accum(float acc[2][NT][4],
        const float* __restrict__ sA, int ast,
        const float* __restrict__ gW, int k_real, int kpad,
        float* __restrict__ sWb, int tid, int wid, int lane)
{
    constexpr int NCOLS = NT * 32;
    const int g   = lane >> 2;
    const int tig = lane & 3;
    const int rb  = (wid & 1) * 32;
    const int cb  = (wid >> 1) * (NT * 8);

    for (int k0 = 0; k0 < kpad; k0 += 64) {
        const int kc = min(64, kpad - k0);
        // stage W chunk into smem (tf32-rounded), zero-pad rows >= k_real
        for (int idx = tid; idx < kc * NCOLS; idx += BLK) {
            const int row = idx / NCOLS;
            const int col = idx - row * NCOLS;
            const int gr  = k0 + row;
            float v = (gr < k_real) ? __ldg(gW + gr * NCOLS + col) : 0.0f;
            sWb[row * WST + col] = tf32r(v);
        }
        __syncthreads();

        for (int k8 = 0; k8 < kc; k8 += 8) {
            unsigned a[2][4];
            const float* Ab = sA + (k0 + k8 + tig);
#pragma unroll
            for (int m = 0; m < 2; ++m) {
                const int r0 = rb + 16 * m + g;
                a[m][0] = __float_as_uint(Ab[r0 * ast]);
                a[m][1] = __float_as_uint(Ab[(r0 + 8) * ast]);
                a[m][2] = __float_as_uint(Ab[r0 * ast + 4]);
                a[m][3] = __float_as_uint(Ab[(r0 + 8) * ast + 4]);
            }
            const float* Bb = sWb + (k8 + tig) * WST + cb + g;
#pragma unroll
            for (int j = 0; j < NT; ++j) {
                const unsigned b0 = __float_as_uint(Bb[8 * j]);
                const unsigned b1 = __float_as_uint(Bb[8 * j + 4 * WST]);
                mma8(acc[0][j], a[0], b0, b1);
                mma8(acc[1][j], a[1], b0, b1);
            }
        }
        __syncthreads();   // all A/W reads done -> safe to overwrite wbuf (and A)
    }
}

template<int NT>
__device__ __forceinline__ void epilogue(float acc[2][NT][4],
        float* __restrict__ sDst, int dst,
        const float* __restrict__ gB, bool do_relu, int wid, int lane)
{
    const int g   = lane >> 2;
    const int tig = lane & 3;
    const int rb  = (wid & 1) * 32;
    const int cb  = (wid >> 1) * (NT * 8);
#pragma unroll
    for (int m = 0; m < 2; ++m) {
        const int r0 = rb + 16 * m + g;
#pragma unroll
        for (int j = 0; j < NT; ++j) {
            const int c = cb + 8 * j + 2 * tig;
            const float b0 = __ldg(gB + c);
            const float b1 = __ldg(gB + c + 1);
            float v00 = acc[m][j][0] + b0, v01 = acc[m][j][1] + b1;
            float v10 = acc[m][j][2] + b0, v11 = acc[m][j][3] + b1;
            if (do_relu) {
                v00 = fmaxf(v00, 0.0f); v01 = fmaxf(v01, 0.0f);
                v10 = fmaxf(v10, 0.0f); v11 = fmaxf(v11, 0.0f);
            }
            sDst[r0 * dst + c]           = tf32r(v00);
            sDst[r0 * dst + c + 1]       = tf32r(v01);
            sDst[(r0 + 8) * dst + c]     = tf32r(v10);
            sDst[(r0 + 8) * dst + c + 1] = tf32r(v11);
        }
    }
}

template<int NT>
__device__ __forceinline__ void zero_acc(float acc[2][NT][4]) {
#pragma unroll
    for (int m = 0; m < 2; ++m)
#pragma unroll
        for (int j = 0; j < NT; ++j)
#pragma unroll
            for (int q = 0; q < 4; ++q) acc[m][j][q] = 0.0f;
}

__global__ void __launch_bounds__(BLK, 1) nerf_fused(Params p) {
    extern __shared__ float sm[];
    float* sH   = sm;                        // [64][260] activations (in-place)
    float* sX   = sH   + TILE * HST;         // [64][68]  xyz posenc (63 + pad0)
    float* sDr  = sX   + TILE * XST;         // [64][36]  dir posenc (27 + pad0)
    float* sWb  = sDr  + TILE * DST;         // [64][264] staged weight chunk
    float* sHid = sWb  + TILE * WST;         // [64][132] rgb hidden
    float* sSig = sHid + TILE * HIDST;       // [64]      sigma

    const int tid  = threadIdx.x;
    const int wid  = tid >> 5;
    const int lane = tid & 31;
    const int p0   = blockIdx.x * TILE;

    // ---- load raw x into wbuf scratch, then positional encodings ----
    float* xr = sWb;
    for (int idx = tid; idx < TILE * 6; idx += BLK)
        xr[idx] = p.x[p0 * 6 + idx];
    __syncthreads();

    // xyz posenc: [p, (sinfx,sinfy,sinfz,cosfx,cosfy,cosfz) x 10], col 63 = 0
    for (int idx = tid; idx < TILE * 64; idx += BLK) {
        const int r = idx >> 6, c = idx & 63;
        float v = 0.0f;
        if (c < 3) v = xr[r * 6 + c];
        else if (c < 63) {
            const int q = c - 3, f = q / 6, rem = q % 6;
            const float ang = xr[r * 6 + (rem % 3)] * (float)(1 << f);
            v = (rem < 3) ? sinf(ang) : cosf(ang);
        }
        sX[r * XST + c] = tf32r(v);
    }
    // dir posenc: 27 real cols, cols 27..31 = 0
    for (int idx = tid; idx < TILE * 32; idx += BLK) {
        const int r = idx >> 5, c = idx & 31;
        float v = 0.0f;
        if (c < 3) v = xr[r * 6 + 3 + c];
        else if (c < 27) {
            const int q = c - 3, f = q / 6, rem = q % 6;
            const float ang = xr[r * 6 + 3 + (rem % 3)] * (float)(1 << f);
            v = (rem < 3) ? sinf(ang) : cosf(ang);
        }
        sDr[r * DST + c] = tf32r(v);
    }
    __syncthreads();

    // ---- layers 0..7 (relu) + final (L==8, no relu) ----
    float acc[2][8][4];
    for (int L = 0; L <= 8; ++L) {
        const float* W;
        const float* B;
        if (L < 8) { W = p.w[L]; B = p.b[L]; }
        else       { W = p.wf;   B = p.bf;   }

        if (L == 8) {
            // sigma = h @ w_sigma + b_sigma   (from layer-7 h, before overwrite)
            __syncthreads();
            const int r = tid >> 2, q = tid & 3;
            const float* hr = sH + r * HST + q * 64;
            const float* ws = p.ws + q * 64;
            float s = 0.0f;
#pragma unroll 8
            for (int i = 0; i < 64; ++i) s = fmaf(hr[i], __ldg(ws + i), s);
            s += __shfl_xor_sync(0xffffffffu, s, 1);
            s += __shfl_xor_sync(0xffffffffu, s, 2);
            if (q == 0) sSig[r] = s + __ldg(p.bs);
        }

        zero_acc<8>(acc);
        if (L == 0) {
            gemm_accum<8>(acc, sX, XST, W, 63, 64, sWb, tid, wid, lane);
        } else {
            if (L == 4)  // skip: [xyz(63) | h(256)] -> rows 0..62 then 63..318
                gemm_accum<8>(acc, sX, XST, W, 63, 64, sWb, tid, wid, lane);
            gemm_accum<8>(acc, sH, HST, (L == 4) ? W + 63 * 256 : W,
                          256, 256, sWb, tid, wid, lane);
        }
        epilogue<8>(acc, sH, HST, B, /*relu=*/(L < 8), wid, lane);
    }

    // ---- rgb1: relu([final(256) | dir(27)] @ w_rgb1 + b_rgb1) -> [64][128] ----
    float a4[2][4][4];
    zero_acc<4>(a4);
    gemm_accum<4>(a4, sH,  HST, p.wr1,             256, 256, sWb, tid, wid, lane);
    gemm_accum<4>(a4, sDr, DST, p.wr1 + 256 * 128,  27,  32, sWb, tid, wid, lane);
    epilogue<4>(a4, sHid, HIDST, p.br1, true, wid, lane);
    __syncthreads();

    // ---- rgb2 + sigmoid + output [N,4] = [rgb, sigma] ----
    if (tid < 192) {
        const int r = tid / 3, c = tid % 3;
        float s = __ldg(p.br2 + c);
        const float* hr = sHid + r * HIDST;
#pragma unroll 8
        for (int k = 0; k < 128; ++k)
            s = fmaf(hr[k], __ldg(p.wr2 + k * 3 + c), s);
        p.out[(p0 + r) * 4 + c] = 1.0f / (1.0f + expf(-s));
    } else {
        const int r = tid - 192;
        p.out[(p0 + r) * 4 + 3] = sSig[r];
    }
}

extern "C" void kernel_launch(void* const* d_in, const int* in_sizes, int n_in,
                              void* d_out, int out_size) {
    Params p;
    p.x = (const float*)d_in[0];
    for (int i = 0; i < 8; ++i) {
        p.w[i] = (const float*)d_in[1 + 2 * i];
        p.b[i] = (const float*)d_in[2 + 2 * i];
    }
    p.wf  = (const float*)d_in[17];
    p.bf  = (const float*)d_in[18];
    p.ws  = (const float*)d_in[19];
    p.bs  = (const float*)d_in[20];
    p.wr1 = (const float*)d_in[21];
    p.br1 = (const float*)d_in[22];
    p.wr2 = (const float*)d_in[23];
    p.br2 = (const float*)d_in[24];
    p.out = (float*)d_out;

    cudaFuncSetAttribute((const void*)nerf_fused,
                         cudaFuncAttributeMaxDynamicSharedMemorySize, SMEM_BYTES);

    const int npts    = in_sizes[0] / 6;
    const int nblocks = npts / TILE;
    nerf_fused<<<nblocks, BLK, SMEM_BYTES>>>(p);
}

// round 8
// speedup vs baseline: 1.9008x; 1.9008x over previous
#include <cuda_runtime.h>

// Fused NeRF MLP forward, tf32 mma.sync.m16n8k8, fp32 accum.
// 64 points/CTA, 256 threads (8 warps), warp tile = 32 rows x (NT*8) cols.
// Weights streamed L2->smem via double-buffered cp.async (32-row chunks),
// B fragments fed by conflict-free LDS.128 via column-permuted+swizzled layout.

#define TILE 64
#define BLK  256

#define HST   260   // activation stride (stride*4 % 128 == 16 -> conflict-free A LDS)
#define XST   68
#define DST   36
#define HIDST 132
#define WROWS 64    // weight buffer rows total (2 x 32-row chunks)

#define SMEM_FLOATS (TILE*(HST + XST + DST + HIDST) + WROWS*256 + TILE)
#define SMEM_BYTES  (SMEM_FLOATS * 4)

struct Params {
    const float* x;
    const float* w[8];
    const float* b[8];
    const float *wf, *bf, *ws, *bs, *wr1, *br1, *wr2, *br2;
    float* out;
};

__device__ __forceinline__ float tf32r(float v) {
    unsigned u;
    asm("cvt.rna.tf32.f32 %0, %1;" : "=r"(u) : "f"(v));
    return __uint_as_float(u);
}

__device__ __forceinline__ void mma8(float c[4], const unsigned a[4],
                                     unsigned b0, unsigned b1) {
    asm volatile(
        "mma.sync.aligned.m16n8k8.row.col.f32.tf32.tf32.f32 "
        "{%0,%1,%2,%3}, {%4,%5,%6,%7}, {%8,%9}, {%0,%1,%2,%3};\n"
        : "+f"(c[0]), "+f"(c[1]), "+f"(c[2]), "+f"(c[3])
        : "r"(a[0]), "r"(a[1]), "r"(a[2]), "r"(a[3]), "r"(b0), "r"(b1));
}

// 16B-chunk swizzle (row = k-row within 32-row buffer).
// NT=8: loads use chunks (2g+h)^s  -> s in {0,1,4,5} keeps phases conflict-free.
// NT=4: loads use chunk  (g)^s     -> s in {0,2,4,6}.
template<int NT>
__device__ __forceinline__ int swz(int row) {
    if (NT == 8) return (row & 1) | ((row & 2) << 1);
    else         return (row & 3) << 1;
}

// MMA over one 32-row staged chunk. Physical col of (tile j, frag col n):
// P(j,n) = cb + n*NT + j  (pure output-column permutation, fixed in epilogue).
template<int NT>
__device__ __forceinline__ void mma_chunk(float acc[2][NT][4],
        const float* __restrict__ sA, int ast, int kb,
        const float* __restrict__ sW, int wid, int lane)
{
    constexpr int NCOLS = NT * 32;
    const int g   = lane >> 2;
    const int tig = lane & 3;
    const int rb  = (wid & 1) * 32;
    const int cb4 = (wid >> 1) * (NT * 2);   // base 16B-chunk index
    const int sg  = swz<NT>(tig);

#pragma unroll
    for (int s = 0; s < 4; ++s) {
        const int k8 = s * 8;
        unsigned a[2][4];
        const float* Ab = sA + kb + k8 + tig;
#pragma unroll
        for (int m = 0; m < 2; ++m) {
            const int r0 = rb + 16 * m + g;
            a[m][0] = __float_as_uint(Ab[r0 * ast]);
            a[m][1] = __float_as_uint(Ab[(r0 + 8) * ast]);
            a[m][2] = __float_as_uint(Ab[r0 * ast + 4]);
            a[m][3] = __float_as_uint(Ab[(r0 + 8) * ast + 4]);
        }
        const float* r0p = sW + (k8 + tig) * NCOLS;
        const float* r1p = sW + (k8 + tig + 4) * NCOLS;

        float b0[NT], b1[NT];
        if (NT == 8) {
            const int c0 = ((cb4 + 2 * g) ^ sg) << 2;
            const int c1 = ((cb4 + 2 * g + 1) ^ sg) << 2;
            float4 q0 = *(const float4*)(r0p + c0);
            float4 q1 = *(const float4*)(r0p + c1);
            float4 q2 = *(const float4*)(r1p + c0);
            float4 q3 = *(const float4*)(r1p + c1);
            b0[0]=q0.x; b0[1]=q0.y; b0[2]=q0.z; b0[3]=q0.w;
            b0[4]=q1.x; b0[5]=q1.y; b0[6]=q1.z; b0[7]=q1.w;
            b1[0]=q2.x; b1[1]=q2.y; b1[2]=q2.z; b1[3]=q2.w;
            b1[4]=q3.x; b1[5]=q3.y; b1[6]=q3.z; b1[7]=q3.w;
        } else {
            const int c0 = ((cb4 + g) ^ sg) << 2;
            float4 q0 = *(const float4*)(r0p + c0);
            float4 q2 = *(const float4*)(r1p + c0);
            b0[0]=q0.x; b0[1]=q0.y; b0[2]=q0.z; b0[3]=q0.w;
            b1[0]=q2.x; b1[1]=q2.y; b1[2]=q2.z; b1[3]=q2.w;
        }
#pragma unroll
        for (int j = 0; j < NT; ++j) {
            const unsigned u0 = __float_as_uint(b0[j]);
            const unsigned u1 = __float_as_uint(b1[j]);
            mma8(acc[0][j], a[0], u0, u1);
            mma8(acc[1][j], a[1], u0, u1);
        }
    }
}

// cp.async one 32-row chunk (raw fp32; tensor core truncates to tf32).
template<int NT>
__device__ __forceinline__ void stage_async(float* __restrict__ buf,
        const float* __restrict__ gW, int kb, int tid)
{
    constexpr int NCOLS = NT * 32;
    constexpr int CPR   = NCOLS / 4;           // 16B chunks per row
#pragma unroll
    for (int i = 0; i < (32 * CPR) / BLK; ++i) {
        const int cl  = tid + i * BLK;
        const int row = cl / CPR;
        const int cs  = cl % CPR;
        const float* src = gW + (kb + row) * NCOLS + cs * 4;
        float* dst = buf + row * NCOLS + ((cs ^ swz<NT>(row)) << 2);
        unsigned sdst = (unsigned)__cvta_generic_to_shared(dst);
        asm volatile("cp.async.cg.shared.global [%0], [%1], 16;\n"
                     :: "r"(sdst), "l"(src));
    }
}

// K exact multiple of 32, no padding: double-buffered cp.async pipeline.
template<int NT>
__device__ __forceinline__ void gemm_async(float acc[2][NT][4],
        const float* __restrict__ sA, int ast,
        const float* __restrict__ gW, int K,
        float* __restrict__ sW0, float* __restrict__ sW1,
        int tid, int wid, int lane)
{
    float* bufs[2] = { sW0, sW1 };
    const int n = K / 32;
    stage_async<NT>(bufs[0], gW, 0, tid);
    asm volatile("cp.async.commit_group;\n");
    for (int c = 0; c < n; ++c) {
        if (c + 1 < n) {
            stage_async<NT>(bufs[(c + 1) & 1], gW, (c + 1) * 32, tid);
            asm volatile("cp.async.commit_group;\n");
            asm volatile("cp.async.wait_group 1;\n");
        } else {
            asm volatile("cp.async.wait_group 0;\n");
        }
        __syncthreads();
        mma_chunk<NT>(acc, sA, ast, c * 32, bufs[c & 1], wid, lane);
        __syncthreads();
    }
}

// Padded small segments (k_real < kpad <= 64): scalar staged, rounded tf32.
template<int NT>
__device__ __forceinline__ void gemm_scalar(float acc[2][NT][4],
        const float* __restrict__ sA, int ast,
        const float* __restrict__ gW, int k_real, int kpad,
        float* __restrict__ sW0, int tid, int wid, int lane)
{
    constexpr int NCOLS = NT * 32;
    for (int kb = 0; kb < kpad; kb += 32) {
        for (int idx = tid; idx < 32 * NCOLS; idx += BLK) {
            const int row = idx / NCOLS;
            const int col = idx - row * NCOLS;
            const int gr  = kb + row;
            const float v = (gr < k_real) ? tf32r(__ldg(gW + gr * NCOLS + col)) : 0.0f;
            const int cs  = col >> 2;
            sW0[row * NCOLS + ((cs ^ swz<NT>(row)) << 2) + (col & 3)] = v;
        }
        __syncthreads();
        mma_chunk<NT>(acc, sA, ast, kb, sW0, wid, lane);
        __syncthreads();
    }
}

template<int NT>
__device__ __forceinline__ void epilogue(float acc[2][NT][4],
        float* __restrict__ sDst, int dst,
        const float* __restrict__ gB, bool do_relu, int wid, int lane)
{
    const int g   = lane >> 2;
    const int tig = lane & 3;
    const int rb  = (wid & 1) * 32;
    const int cb  = (wid >> 1) * (NT * 8);
#pragma unroll
    for (int m = 0; m < 2; ++m) {
        const int r0 = rb + 16 * m + g;
#pragma unroll
        for (int j = 0; j < NT; ++j) {
            const int c0 = cb + (2 * tig) * NT + j;        // P(j, 2*tig)
            const int c1 = cb + (2 * tig + 1) * NT + j;    // P(j, 2*tig+1)
            const float b0 = __ldg(gB + c0);
            const float b1 = __ldg(gB + c1);
            float v00 = acc[m][j][0] + b0, v01 = acc[m][j][1] + b1;
            float v10 = acc[m][j][2] + b0, v11 = acc[m][j][3] + b1;
            if (do_relu) {
                v00 = fmaxf(v00, 0.0f); v01 = fmaxf(v01, 0.0f);
                v10 = fmaxf(v10, 0.0f); v11 = fmaxf(v11, 0.0f);
            }
            sDst[r0 * dst + c0]       = tf32r(v00);
            sDst[r0 * dst + c1]       = tf32r(v01);
            sDst[(r0 + 8) * dst + c0] = tf32r(v10);
            sDst[(r0 + 8) * dst + c1] = tf32r(v11);
        }
    }
}

template<int NT>
__device__ __forceinline__ void zero_acc(float acc[2][NT][4]) {
#pragma unroll
    for (int m = 0; m < 2; ++m)
#pragma unroll
        for (int j = 0; j < NT; ++j)
#pragma unroll
            for (int q = 0; q < 4; ++q) acc[m][j][q] = 0.0f;
}

__global__ void __launch_bounds__(BLK, 1) nerf_fused(Params p) {
    extern __shared__ float sm[];
    float* sH   = sm;                       // [64][260]
    float* sX   = sH   + TILE * HST;        // [64][68]
    float* sDr  = sX   + TILE * XST;        // [64][36]
    float* sW0  = sDr  + TILE * DST;        // [32][256] chunk buf 0
    float* sW1  = sW0  + 32 * 256;          // [32][256] chunk buf 1
    float* sHid = sW1  + 32 * 256;          // [64][132]
    float* sSig = sHid + TILE * HIDST;      // [64]

    const int tid  = threadIdx.x;
    const int wid  = tid >> 5;
    const int lane = tid & 31;
    const int p0   = blockIdx.x * TILE;

    // ---- raw x into weight-buf scratch, then positional encodings ----
    float* xr = sW0;
    for (int idx = tid; idx < TILE * 6; idx += BLK)
        xr[idx] = p.x[p0 * 6 + idx];
    __syncthreads();

    for (int idx = tid; idx < TILE * 64; idx += BLK) {
        const int r = idx >> 6, c = idx & 63;
        float v = 0.0f;
        if (c < 3) v = xr[r * 6 + c];
        else if (c < 63) {
            const int q = c - 3, f = q / 6, rem = q % 6;
            const float ang = xr[r * 6 + (rem % 3)] * (float)(1 << f);
            v = (rem < 3) ? sinf(ang) : cosf(ang);
        }
        sX[r * XST + c] = tf32r(v);
    }
    for (int idx = tid; idx < TILE * 32; idx += BLK) {
        const int r = idx >> 5, c = idx & 31;
        float v = 0.0f;
        if (c < 3) v = xr[r * 6 + 3 + c];
        else if (c < 27) {
            const int q = c - 3, f = q / 6, rem = q % 6;
            const float ang = xr[r * 6 + 3 + (rem % 3)] * (float)(1 << f);
            v = (rem < 3) ? sinf(ang) : cosf(ang);
        }
        sDr[r * DST + c] = tf32r(v);
    }
    __syncthreads();

    // ---- layers 0..7 (relu) + final (no relu) ----
    float acc[2][8][4];
    for (int L = 0; L <= 8; ++L) {
        const float* W = (L < 8) ? p.w[L] : p.wf;
        const float* B = (L < 8) ? p.b[L] : p.bf;

        if (L == 8) {
            // sigma from layer-7 h (before overwrite)
            __syncthreads();
            const int r = tid >> 2, q = tid & 3;
            const float* hr = sH + r * HST + q * 64;
            const float* ws = p.ws + q * 64;
            float s = 0.0f;
#pragma unroll 8
            for (int i = 0; i < 64; ++i) s = fmaf(hr[i], __ldg(ws + i), s);
            s += __shfl_xor_sync(0xffffffffu, s, 1);
            s += __shfl_xor_sync(0xffffffffu, s, 2);
            if (q == 0) sSig[r] = s + __ldg(p.bs);
            __syncthreads();
        }

        zero_acc<8>(acc);
        if (L == 0) {
            gemm_scalar<8>(acc, sX, XST, W, 63, 64, sW0, tid, wid, lane);
        } else {
            if (L == 4)
                gemm_scalar<8>(acc, sX, XST, W, 63, 64, sW0, tid, wid, lane);
            gemm_async<8>(acc, sH, HST, (L == 4) ? W + 63 * 256 : W,
                          256, sW0, sW1, tid, wid, lane);
        }
        epilogue<8>(acc, sH, HST, B, /*relu=*/(L < 8), wid, lane);
    }

    // ---- rgb1: relu([final(256) | dir(27)] @ w_rgb1 + b_rgb1) ----
    float a4[2][4][4];
    zero_acc<4>(a4);
    gemm_async<4>(a4, sH, HST, p.wr1, 256, sW0, sW1, tid, wid, lane);
    gemm_scalar<4>(a4, sDr, DST, p.wr1 + 256 * 128, 27, 32, sW0, tid, wid, lane);
    epilogue<4>(a4, sHid, HIDST, p.br1, true, wid, lane);
    __syncthreads();

    // ---- rgb2 + sigmoid + output [N,4] = [rgb, sigma] ----
    if (tid < 192) {
        const int r = tid / 3, c = tid % 3;
        float s = __ldg(p.br2 + c);
        const float* hr = sHid + r * HIDST;
#pragma unroll 8
        for (int k = 0; k < 128; ++k)
            s = fmaf(hr[k], __ldg(p.wr2 + k * 3 + c), s);
        p.out[(p0 + r) * 4 + c] = 1.0f / (1.0f + expf(-s));
    } else {
        const int r = tid - 192;
        p.out[(p0 + r) * 4 + 3] = sSig[r];
    }
}

extern "C" void kernel_launch(void* const* d_in, const int* in_sizes, int n_in,
                              void* d_out, int out_size) {
    Params p;
    p.x = (const float*)d_in[0];
    for (int i = 0; i < 8; ++i) {
        p.w[i] = (const float*)d_in[1 + 2 * i];
        p.b[i] = (const float*)d_in[2 + 2 * i];
    }
    p.wf  = (const float*)d_in[17];
    p.bf  = (const float*)d_in[18];
    p.ws  = (const float*)d_in[19];
    p.bs  = (const float*)d_in[20];
    p.wr1 = (const float*)d_in[21];
    p.br1 = (const float*)d_in[22];
    p.wr2 = (const float*)d_in[23];
    p.br2 = (const float*)d_in[24];
    p.out = (float*)d_out;

    cudaFuncSetAttribute((const void*)nerf_fused,
                         cudaFuncAttributeMaxDynamicSharedMemorySize, SMEM_BYTES);

    const int npts    = in_sizes[0] / 6;
    const int nblocks = npts / TILE;
    nerf_fused<<<nblocks, BLK, SMEM_BYTES>>>(p);
}

// round 9
// speedup vs baseline: 3.6694x; 1.9305x over previous
#include <cuda_runtime.h>
#include <cuda_fp16.h>

// Fused NeRF MLP forward, fp16 mma.sync.m16n8k16, fp32 accum.
// 64 points/CTA, 256 threads (8 warps), warp tile 32 rows x (NT*8) cols.
// Weights pre-converted per launch into a padded, k-pair-interleaved fp16
// __device__ buffer; streamed L2->smem via double-buffered cp.async.

#define TILE 64
#define BLK  256

// strides in HALF units (word stride % 32 == 4 -> conflict-free A loads)
#define HSTH  264
#define XSTH  72
#define DSTH  72
#define HIDH  136

// ---- packed fp16 weight buffer (halves), layout [(k/2)][N][2] per segment ----
#define SEG0   0        // L0 xyz     64 x 256
#define SEG1   16384    // L1        256 x 256
#define SEG2   81920
#define SEG3   147456
#define SEG4X  212992   // L4 xyz     64 x 256
#define SEG4H  229376   // L4 h      256 x 256
#define SEG5   294912
#define SEG6   360448
#define SEG7   425984
#define SEGF   491520   // final     256 x 256
#define SEGR1  557056   // rgb1 h    256 x 128
#define SEGR1D 589824   // rgb1 dir   64 x 128
#define WH_TOTAL 598016

__device__ __half g_wh[WH_TOTAL];

struct Params {
    const float* x;
    const float* b[8];
    const float *bf, *ws, *bs, *br1, *wr2, *br2;
    float* out;
};

struct ConvSeg { const float* src; int k_real; int N; int dst_off; int sz; };
struct ConvParams { ConvSeg s[12]; };

__global__ void conv_weights(ConvParams cp) {
    const int idx = blockIdx.x * blockDim.x + threadIdx.x;
    if (idx >= WH_TOTAL) return;
    // find segment (offsets ascending)
    int si = 0;
#pragma unroll
    for (int i = 1; i < 12; ++i)
        if (idx >= cp.s[i].dst_off) si = i;
    const ConvSeg g = cp.s[si];
    const int local = idx - g.dst_off;
    const int t  = local >> 1;
    const int n  = t % g.N;
    const int pr = t / g.N;
    const int k  = 2 * pr + (local & 1);
    const float v = (k < g.k_real) ? g.src[k * g.N + n] : 0.0f;
    g_wh[idx] = __float2half_rn(v);
}

__device__ __forceinline__ void mma16(float c[4], const unsigned a[4],
                                      unsigned b0, unsigned b1) {
    asm volatile(
        "mma.sync.aligned.m16n8k16.row.col.f32.f16.f16.f32 "
        "{%0,%1,%2,%3}, {%4,%5,%6,%7}, {%8,%9}, {%0,%1,%2,%3};\n"
        : "+f"(c[0]), "+f"(c[1]), "+f"(c[2]), "+f"(c[3])
        : "r"(a[0]), "r"(a[1]), "r"(a[2]), "r"(a[3]), "r"(b0), "r"(b1));
}

// 16B-chunk swizzle keyed on pair-row mod 4.
template<int NT>
__device__ __forceinline__ int swz(int r) {
    if (NT == 8) return (r & 1) | ((r & 2) << 1);   // {0,1,4,5}
    else         return (r & 3) << 1;                // {0,2,4,6}
}

// One 64-k-row chunk (32 pair-rows). sW = staged weights, word array
// [pair_row][NCOLS words], column-permuted P(j,n)=cb+n*NT+j + swizzled.
template<int NT>
__device__ __forceinline__ void mma_chunk(float acc[2][NT][4],
        const __half* __restrict__ sA, int astH, int kb,
        const float* __restrict__ sW, int wid, int lane)
{
    constexpr int NCOLS = NT * 32;
    const int g   = lane >> 2;
    const int tig = lane & 3;
    const int rb  = (wid & 1) * 32;
    const int cb4 = (wid >> 1) * (NT * 2);
    const int sg  = swz<NT>(tig);
    const int kw  = kb >> 1;   // word base into A

#pragma unroll
    for (int s = 0; s < 4; ++s) {
        const int w0 = kw + 8 * s + tig;
        unsigned a[2][4];
#pragma unroll
        for (int m = 0; m < 2; ++m) {
            const int r0 = rb + 16 * m + g;
            a[m][0] = *(const unsigned*)(sA + r0 * astH        + 2 * w0);
            a[m][1] = *(const unsigned*)(sA + (r0 + 8) * astH  + 2 * w0);
            a[m][2] = *(const unsigned*)(sA + r0 * astH        + 2 * (w0 + 4));
            a[m][3] = *(const unsigned*)(sA + (r0 + 8) * astH  + 2 * (w0 + 4));
        }
        const float* r0p = sW + (8 * s + tig) * NCOLS;
        const float* r1p = sW + (8 * s + tig + 4) * NCOLS;

        unsigned b0[NT], b1[NT];
        if (NT == 8) {
            const int c0 = ((cb4 + 2 * g) ^ sg) << 2;
            const int c1 = ((cb4 + 2 * g + 1) ^ sg) << 2;
            float4 q0 = *(const float4*)(r0p + c0);
            float4 q1 = *(const float4*)(r0p + c1);
            float4 q2 = *(const float4*)(r1p + c0);
            float4 q3 = *(const float4*)(r1p + c1);
            b0[0]=__float_as_uint(q0.x); b0[1]=__float_as_uint(q0.y);
            b0[2]=__float_as_uint(q0.z); b0[3]=__float_as_uint(q0.w);
            b0[4]=__float_as_uint(q1.x); b0[5]=__float_as_uint(q1.y);
            b0[6]=__float_as_uint(q1.z); b0[7]=__float_as_uint(q1.w);
            b1[0]=__float_as_uint(q2.x); b1[1]=__float_as_uint(q2.y);
            b1[2]=__float_as_uint(q2.z); b1[3]=__float_as_uint(q2.w);
            b1[4]=__float_as_uint(q3.x); b1[5]=__float_as_uint(q3.y);
            b1[6]=__float_as_uint(q3.z); b1[7]=__float_as_uint(q3.w);
        } else {
            const int c0 = ((cb4 + g) ^ sg) << 2;
            float4 q0 = *(const float4*)(r0p + c0);
            float4 q2 = *(const float4*)(r1p + c0);
            b0[0]=__float_as_uint(q0.x); b0[1]=__float_as_uint(q0.y);
            b0[2]=__float_as_uint(q0.z); b0[3]=__float_as_uint(q0.w);
            b1[0]=__float_as_uint(q2.x); b1[1]=__float_as_uint(q2.y);
            b1[2]=__float_as_uint(q2.z); b1[3]=__float_as_uint(q2.w);
        }
#pragma unroll
        for (int j = 0; j < NT; ++j) {
            mma16(acc[0][j], a[0], b0[j], b1[j]);
            mma16(acc[1][j], a[1], b0[j], b1[j]);
        }
    }
}

// cp.async one 64-k-row chunk (32 pair-rows) from packed fp16 weights.
template<int NT>
__device__ __forceinline__ void stage_async(float* __restrict__ buf,
        const __half* __restrict__ gW, int pr_base, int tid)
{
    constexpr int NCOLS = NT * 32;           // words per pair-row
    constexpr int CPR   = NCOLS / 4;         // 16B chunks per pair-row
#pragma unroll
    for (int i = 0; i < (32 * CPR) / BLK; ++i) {
        const int cl  = tid + i * BLK;
        const int pr  = cl / CPR;
        const int cs  = cl % CPR;
        const __half* src = gW + (pr_base + pr) * (NCOLS * 2) + cs * 8;
        float* dst = buf + pr * NCOLS + ((cs ^ swz<NT>(pr & 3)) << 2);
        unsigned sdst = (unsigned)__cvta_generic_to_shared(dst);
        asm volatile("cp.async.cg.shared.global [%0], [%1], 16;\n"
                     :: "r"(sdst), "l"(src));
    }
}

// K multiple of 64; double-buffered pipeline.
template<int NT>
__device__ __forceinline__ void gemm_async(float acc[2][NT][4],
        const __half* __restrict__ sA, int astH,
        const __half* __restrict__ gW, int K,
        float* __restrict__ sW0, float* __restrict__ sW1,
        int tid, int wid, int lane)
{
    float* bufs[2] = { sW0, sW1 };
    const int n = K / 64;
    stage_async<NT>(bufs[0], gW, 0, tid);
    asm volatile("cp.async.commit_group;\n");
    for (int c = 0; c < n; ++c) {
        if (c + 1 < n) {
            stage_async<NT>(bufs[(c + 1) & 1], gW, (c + 1) * 32, tid);
            asm volatile("cp.async.commit_group;\n");
            asm volatile("cp.async.wait_group 1;\n");
        } else {
            asm volatile("cp.async.wait_group 0;\n");
        }
        __syncthreads();
        mma_chunk<NT>(acc, sA, astH, c * 64, bufs[c & 1], wid, lane);
        __syncthreads();
    }
}

template<int NT>
__device__ __forceinline__ void epilogue(float acc[2][NT][4],
        __half* __restrict__ sDst, int dstH,
        const float* __restrict__ gB, bool do_relu, int wid, int lane)
{
    const int g   = lane >> 2;
    const int tig = lane & 3;
    const int rb  = (wid & 1) * 32;
    const int cb  = (wid >> 1) * (NT * 8);
#pragma unroll
    for (int m = 0; m < 2; ++m) {
        const int r0 = rb + 16 * m + g;
#pragma unroll
        for (int j = 0; j < NT; ++j) {
            const int c0 = cb + (2 * tig) * NT + j;
            const int c1 = cb + (2 * tig + 1) * NT + j;
            const float b0 = __ldg(gB + c0);
            const float b1 = __ldg(gB + c1);
            float v00 = acc[m][j][0] + b0, v01 = acc[m][j][1] + b1;
            float v10 = acc[m][j][2] + b0, v11 = acc[m][j][3] + b1;
            if (do_relu) {
                v00 = fmaxf(v00, 0.0f); v01 = fmaxf(v01, 0.0f);
                v10 = fmaxf(v10, 0.0f); v11 = fmaxf(v11, 0.0f);
            }
            sDst[r0 * dstH + c0]       = __float2half_rn(v00);
            sDst[r0 * dstH + c1]       = __float2half_rn(v01);
            sDst[(r0 + 8) * dstH + c0] = __float2half_rn(v10);
            sDst[(r0 + 8) * dstH + c1] = __float2half_rn(v11);
        }
    }
}

template<int NT>
__device__ __forceinline__ void zero_acc(float acc[2][NT][4]) {
#pragma unroll
    for (int m = 0; m < 2; ++m)
#pragma unroll
        for (int j = 0; j < NT; ++j)
#pragma unroll
            for (int q = 0; q < 4; ++q) acc[m][j][q] = 0.0f;
}

// smem byte offsets (16B aligned)
#define OFF_H    0
#define OFF_X    (OFF_H + TILE*HSTH*2)        // 33792
#define OFF_D    (OFF_X + TILE*XSTH*2)        // +9216
#define OFF_W0   (OFF_D + TILE*DSTH*2)        // +9216
#define OFF_W1   (OFF_W0 + 32*256*4)          // +32768
#define OFF_HID  (OFF_W1 + 32*256*4)          // +32768
#define OFF_SIG  (OFF_HID + TILE*HIDH*2)      // +17408
#define SMEM_BYTES (OFF_SIG + TILE*4)

__global__ void __launch_bounds__(BLK, 1) nerf_fused(Params p) {
    extern __shared__ unsigned char smraw[];
    __half* sH   = (__half*)(smraw + OFF_H);
    __half* sX   = (__half*)(smraw + OFF_X);
    __half* sDr  = (__half*)(smraw + OFF_D);
    float*  sW0  = (float*) (smraw + OFF_W0);
    float*  sW1  = (float*) (smraw + OFF_W1);
    __half* sHid = (__half*)(smraw + OFF_HID);
    float*  sSig = (float*) (smraw + OFF_SIG);

    const int tid  = threadIdx.x;
    const int wid  = tid >> 5;
    const int lane = tid & 31;
    const int p0   = blockIdx.x * TILE;

    // ---- raw x into weight-buf scratch, then positional encodings ----
    float* xr = sW0;
    for (int idx = tid; idx < TILE * 6; idx += BLK)
        xr[idx] = p.x[p0 * 6 + idx];
    __syncthreads();

    for (int idx = tid; idx < TILE * 64; idx += BLK) {
        const int r = idx >> 6, c = idx & 63;
        float v = 0.0f;
        if (c < 3) v = xr[r * 6 + c];
        else if (c < 63) {
            const int q = c - 3, f = q / 6, rem = q % 6;
            const float ang = xr[r * 6 + (rem % 3)] * (float)(1 << f);
            v = (rem < 3) ? sinf(ang) : cosf(ang);
        }
        sX[r * XSTH + c] = __float2half_rn(v);
    }
    for (int idx = tid; idx < TILE * 64; idx += BLK) {
        const int r = idx >> 6, c = idx & 63;
        float v = 0.0f;
        if (c < 3) v = xr[r * 6 + 3 + c];
        else if (c < 27) {
            const int q = c - 3, f = q / 6, rem = q % 6;
            const float ang = xr[r * 6 + 3 + (rem % 3)] * (float)(1 << f);
            v = (rem < 3) ? sinf(ang) : cosf(ang);
        }
        sDr[r * DSTH + c] = __float2half_rn(v);
    }
    __syncthreads();

    const __half* wsegs[9] = { g_wh + SEG1, g_wh + SEG2, g_wh + SEG3,
                               g_wh + SEG4H, g_wh + SEG5, g_wh + SEG6,
                               g_wh + SEG7, g_wh + SEGF, 0 };

    // ---- layers 0..7 (relu) + final (no relu) ----
    float acc[2][8][4];
    for (int L = 0; L <= 8; ++L) {
        const float* B = (L < 8) ? p.b[L] : p.bf;

        if (L == 8) {
            // sigma from layer-7 h (before overwrite)
            __syncthreads();
            const int r = tid >> 2, q = tid & 3;
            const __half* hr = sH + r * HSTH + q * 64;
            const float* ws = p.ws + q * 64;
            float s = 0.0f;
#pragma unroll 8
            for (int i = 0; i < 64; ++i)
                s = fmaf(__half2float(hr[i]), __ldg(ws + i), s);
            s += __shfl_xor_sync(0xffffffffu, s, 1);
            s += __shfl_xor_sync(0xffffffffu, s, 2);
            if (q == 0) sSig[r] = s + __ldg(p.bs);
            __syncthreads();
        }

        zero_acc<8>(acc);
        if (L == 0) {
            gemm_async<8>(acc, sX, XSTH, g_wh + SEG0, 64, sW0, sW1, tid, wid, lane);
        } else {
            if (L == 4)
                gemm_async<8>(acc, sX, XSTH, g_wh + SEG4X, 64, sW0, sW1, tid, wid, lane);
            gemm_async<8>(acc, sH, HSTH, wsegs[L - 1], 256, sW0, sW1, tid, wid, lane);
        }
        epilogue<8>(acc, sH, HSTH, B, /*relu=*/(L < 8), wid, lane);
    }

    // ---- rgb1: relu([final(256) | dir(27 pad 64)] @ w_rgb1 + b_rgb1) ----
    float a4[2][4][4];
    zero_acc<4>(a4);
    gemm_async<4>(a4, sH,  HSTH, g_wh + SEGR1,  256, sW0, sW1, tid, wid, lane);
    gemm_async<4>(a4, sDr, DSTH, g_wh + SEGR1D,  64, sW0, sW1, tid, wid, lane);
    epilogue<4>(a4, sHid, HIDH, p.br1, true, wid, lane);
    __syncthreads();

    // ---- rgb2 + sigmoid + output [N,4] = [rgb, sigma] ----
    if (tid < 192) {
        const int r = tid / 3, c = tid % 3;
        float s = __ldg(p.br2 + c);
        const __half* hr = sHid + r * HIDH;
#pragma unroll 8
        for (int k = 0; k < 128; ++k)
            s = fmaf(__half2float(hr[k]), __ldg(p.wr2 + k * 3 + c), s);
        p.out[(p0 + r) * 4 + c] = 1.0f / (1.0f + expf(-s));
    } else {
        const int r = tid - 192;
        p.out[(p0 + r) * 4 + 3] = sSig[r];
    }
}

extern "C" void kernel_launch(void* const* d_in, const int* in_sizes, int n_in,
                              void* d_out, int out_size) {
    Params p;
    p.x = (const float*)d_in[0];
    const float* w[8];
    for (int i = 0; i < 8; ++i) {
        w[i]   = (const float*)d_in[1 + 2 * i];
        p.b[i] = (const float*)d_in[2 + 2 * i];
    }
    const float* wf  = (const float*)d_in[17];
    p.bf  = (const float*)d_in[18];
    p.ws  = (const float*)d_in[19];
    p.bs  = (const float*)d_in[20];
    const float* wr1 = (const float*)d_in[21];
    p.br1 = (const float*)d_in[22];
    p.wr2 = (const float*)d_in[23];
    p.br2 = (const float*)d_in[24];
    p.out = (float*)d_out;

    ConvParams cp;
    cp.s[0]  = { w[0],            63, 256, SEG0,   16384 };
    cp.s[1]  = { w[1],           256, 256, SEG1,   65536 };
    cp.s[2]  = { w[2],           256, 256, SEG2,   65536 };
    cp.s[3]  = { w[3],           256, 256, SEG3,   65536 };
    cp.s[4]  = { w[4],            63, 256, SEG4X,  16384 };
    cp.s[5]  = { w[4] + 63 * 256, 256, 256, SEG4H, 65536 };
    cp.s[6]  = { w[5],           256, 256, SEG5,   65536 };
    cp.s[7]  = { w[6],           256, 256, SEG6,   65536 };
    cp.s[8]  = { w[7],           256, 256, SEG7,   65536 };
    cp.s[9]  = { wf,             256, 256, SEGF,   65536 };
    cp.s[10] = { wr1,            256, 128, SEGR1,  32768 };
    cp.s[11] = { wr1 + 256*128,   27, 128, SEGR1D,  8192 };

    conv_weights<<<(WH_TOTAL + 511) / 512, 512>>>(cp);

    cudaFuncSetAttribute((const void*)nerf_fused,
                         cudaFuncAttributeMaxDynamicSharedMemorySize, SMEM_BYTES);

    const int npts    = in_sizes[0] / 6;
    const int nblocks = npts / TILE;
    nerf_fused<<<nblocks, BLK, SMEM_BYTES>>>(p);
}

// round 10
// speedup vs baseline: 4.0798x; 1.1118x over previous
#include <cuda_runtime.h>
#include <cuda_fp16.h>

// Fused NeRF MLP forward, fp16 mma.sync.m16n8k16, fp32 accum.
// 64 points/CTA, 512 threads (16 warps), warp tile 32 rows x 32 cols.
// A fragments via ldmatrix.x4; B via permuted+swizzled LDS.128.
// Weights pre-packed fp16 [(k/2)][N][2]; triple-buffered cp.async staging.

#define TILE 64
#define BLK  512

// strides in halves (row stride bytes % 128 == 16 -> conflict-free ldmatrix)
#define HSTH  264
#define XSTH  72
#define DSTH  72
#define HIDH  136

// ---- packed fp16 weight buffer (halves), layout [(k/2)][N][2] per segment ----
#define SEG0   0        // L0 xyz     64 x 256
#define SEG1   16384
#define SEG2   81920
#define SEG3   147456
#define SEG4X  212992   // L4 xyz     64 x 256
#define SEG4H  229376
#define SEG5   294912
#define SEG6   360448
#define SEG7   425984
#define SEGF   491520
#define SEGR1  557056   // rgb1 h    256 x 128
#define SEGR1D 589824   // rgb1 dir   64 x 128
#define WH_TOTAL 598016

__device__ __half g_wh[WH_TOTAL];

struct Params {
    const float* x;
    const float* b[8];
    const float *bf, *ws, *bs, *br1, *wr2, *br2;
    float* out;
};

struct ConvSeg { const float* src; int k_real; int N; int dst_off; int sz; };
struct ConvParams { ConvSeg s[12]; };

__global__ void conv_weights(ConvParams cp) {
    const int idx = blockIdx.x * blockDim.x + threadIdx.x;
    if (idx >= WH_TOTAL) return;
    int si = 0;
#pragma unroll
    for (int i = 1; i < 12; ++i)
        if (idx >= cp.s[i].dst_off) si = i;
    const ConvSeg g = cp.s[si];
    const int local = idx - g.dst_off;
    const int t  = local >> 1;
    const int n  = t % g.N;
    const int pr = t / g.N;
    const int k  = 2 * pr + (local & 1);
    const float v = (k < g.k_real) ? g.src[k * g.N + n] : 0.0f;
    g_wh[idx] = __float2half_rn(v);
}

__device__ __forceinline__ void mma16(float c[4], const unsigned a[4],
                                      unsigned b0, unsigned b1) {
    asm volatile(
        "mma.sync.aligned.m16n8k16.row.col.f32.f16.f16.f32 "
        "{%0,%1,%2,%3}, {%4,%5,%6,%7}, {%8,%9}, {%0,%1,%2,%3};\n"
        : "+f"(c[0]), "+f"(c[1]), "+f"(c[2]), "+f"(c[3])
        : "r"(a[0]), "r"(a[1]), "r"(a[2]), "r"(a[3]), "r"(b0), "r"(b1));
}

__device__ __forceinline__ void ldsm_x4(unsigned r[4], const __half* p) {
    unsigned addr = (unsigned)__cvta_generic_to_shared(p);
    asm volatile("ldmatrix.sync.aligned.m8n8.x4.shared.b16 {%0,%1,%2,%3}, [%4];\n"
        : "=r"(r[0]), "=r"(r[1]), "=r"(r[2]), "=r"(r[3]) : "r"(addr));
}

// One 64-k-row chunk (32 pair-rows). sW words: [pair_row][NCW], column
// permutation P(j,n) = cb + n*4 + j, 16B-chunk XOR swizzle sg = (pr&3)<<1.
template<int NCW>
__device__ __forceinline__ void mma_chunk(float acc[2][4][4],
        const __half* __restrict__ sA, int astH, int kbH,
        const float* __restrict__ sW, int wid, int lane)
{
    const int g    = lane >> 2;
    const int tig  = lane & 3;
    const int mat  = lane >> 3;
    const int arow = ((mat & 1) << 3) + (lane & 7);
    const int akof = (mat >> 1) << 3;
    const int rb   = (wid & 1) * 32;
    const int cb4  = (wid >> 1) * 8;          // 16B-chunk base within pair-row
    const int c0   = ((cb4 + g) ^ (tig << 1)) << 2;   // word offset

#pragma unroll
    for (int s = 0; s < 4; ++s) {
        unsigned a[2][4];
#pragma unroll
        for (int m = 0; m < 2; ++m) {
            const __half* ap = sA + (rb + 16 * m + arow) * astH
                                  + kbH + 16 * s + akof;
            ldsm_x4(a[m], ap);
        }
        const float* r0p = sW + (8 * s + tig) * NCW;
        const float* r1p = r0p + 4 * NCW;
        const float4 q0 = *(const float4*)(r0p + c0);
        const float4 q1 = *(const float4*)(r1p + c0);
        const unsigned* b0 = (const unsigned*)&q0;
        const unsigned* b1 = (const unsigned*)&q1;
#pragma unroll
        for (int j = 0; j < 4; ++j) {
            mma16(acc[0][j], a[0], b0[j], b1[j]);
            mma16(acc[1][j], a[1], b0[j], b1[j]);
        }
    }
}

// cp.async one 64-k-row chunk (32 pair-rows) from packed fp16 weights.
template<int NCW>
__device__ __forceinline__ void stage_async(float* __restrict__ buf,
        const __half* __restrict__ gW, int pr_base, int tid)
{
    constexpr int CPR = NCW / 4;
    constexpr int IT  = (32 * CPR) / BLK;
#pragma unroll
    for (int i = 0; i < IT; ++i) {
        const int cl = tid + i * BLK;
        const int pr = cl / CPR;
        const int cs = cl % CPR;
        const __half* src = gW + (pr_base + pr) * (2 * NCW) + cs * 8;
        float* dst = buf + pr * NCW + ((cs ^ ((pr & 3) << 1)) << 2);
        unsigned sdst = (unsigned)__cvta_generic_to_shared(dst);
        asm volatile("cp.async.cg.shared.global [%0], [%1], 16;\n"
                     :: "r"(sdst), "l"(src));
    }
}

// K multiple of 64; triple-buffered, one barrier per chunk.
template<int NCW>
__device__ __forceinline__ void gemm_async(float acc[2][4][4],
        const __half* __restrict__ sA, int astH,
        const __half* __restrict__ gW, int K,
        float* __restrict__ w0, float* __restrict__ w1, float* __restrict__ w2,
        int tid, int wid, int lane, bool active)
{
    float* bufs[3] = { w0, w1, w2 };
    const int n = K / 64;
    stage_async<NCW>(bufs[0], gW, 0, tid);
    asm volatile("cp.async.commit_group;\n");
    if (n > 1) {
        stage_async<NCW>(bufs[1], gW, 32, tid);
        asm volatile("cp.async.commit_group;\n");
    }
    for (int c = 0; c < n; ++c) {
        if (c + 1 < n) asm volatile("cp.async.wait_group 1;\n");
        else           asm volatile("cp.async.wait_group 0;\n");
        __syncthreads();
        if (active) mma_chunk<NCW>(acc, sA, astH, c * 64, bufs[c % 3], wid, lane);
        if (c + 2 < n) {
            stage_async<NCW>(bufs[(c + 2) % 3], gW, (c + 2) * 32, tid);
            asm volatile("cp.async.commit_group;\n");
        }
    }
    __syncthreads();
}

// 8 contiguous output columns per thread-row -> one STS.128 per row.
__device__ __forceinline__ void epilogue(float acc[2][4][4],
        __half* __restrict__ sDst, int dstH,
        const float* __restrict__ gB, bool do_relu, int wid, int lane)
{
    const int g   = lane >> 2;
    const int tig = lane & 3;
    const int rb  = (wid & 1) * 32;
    const int cb  = (wid >> 1) * 32;
    const int cbase = cb + 8 * tig;
    const float4 bA = *(const float4*)(gB + cbase);
    const float4 bB = *(const float4*)(gB + cbase + 4);
    const float bias[8] = { bA.x, bA.y, bA.z, bA.w, bB.x, bB.y, bB.z, bB.w };
#pragma unroll
    for (int m = 0; m < 2; ++m) {
#pragma unroll
        for (int h = 0; h < 2; ++h) {
            const int row = rb + 16 * m + 8 * h + g;
            __half hv[8];
#pragma unroll
            for (int j = 0; j < 4; ++j) {
                float v0 = acc[m][j][2 * h + 0] + bias[j];
                float v1 = acc[m][j][2 * h + 1] + bias[4 + j];
                if (do_relu) { v0 = fmaxf(v0, 0.0f); v1 = fmaxf(v1, 0.0f); }
                hv[j]     = __float2half_rn(v0);
                hv[4 + j] = __float2half_rn(v1);
            }
            *(uint4*)(sDst + row * dstH + cbase) = *(const uint4*)hv;
        }
    }
}

__device__ __forceinline__ void zero_acc(float acc[2][4][4]) {
#pragma unroll
    for (int m = 0; m < 2; ++m)
#pragma unroll
        for (int j = 0; j < 4; ++j)
#pragma unroll
            for (int q = 0; q < 4; ++q) acc[m][j][q] = 0.0f;
}

// smem byte offsets (16B aligned)
#define OFF_H    0
#define OFF_X    (OFF_H + TILE*HSTH*2)         // 33792
#define OFF_D    (OFF_X + TILE*XSTH*2)
#define OFF_W0   (OFF_D + TILE*DSTH*2)
#define OFF_W1   (OFF_W0 + 32*256*4)
#define OFF_W2   (OFF_W1 + 32*256*4)
#define OFF_HID  (OFF_W2 + 32*256*4)
#define OFF_SIG  (OFF_HID + TILE*HIDH*2)
#define SMEM_BYTES (OFF_SIG + TILE*4)

__global__ void __launch_bounds__(BLK, 1) nerf_fused(Params p) {
    extern __shared__ unsigned char smraw[];
    __half* sH   = (__half*)(smraw + OFF_H);
    __half* sX   = (__half*)(smraw + OFF_X);
    __half* sDr  = (__half*)(smraw + OFF_D);
    float*  sW0  = (float*) (smraw + OFF_W0);
    float*  sW1  = (float*) (smraw + OFF_W1);
    float*  sW2  = (float*) (smraw + OFF_W2);
    __half* sHid = (__half*)(smraw + OFF_HID);
    float*  sSig = (float*) (smraw + OFF_SIG);

    const int tid  = threadIdx.x;
    const int wid  = tid >> 5;
    const int lane = tid & 31;
    const int p0   = blockIdx.x * TILE;

    // ---- raw x into weight-buf scratch, then positional encodings ----
    float* xr = sW0;
    for (int idx = tid; idx < TILE * 6; idx += BLK)
        xr[idx] = p.x[p0 * 6 + idx];
    __syncthreads();

    for (int idx = tid; idx < TILE * 64; idx += BLK) {
        const int r = idx >> 6, c = idx & 63;
        float v = 0.0f;
        if (c < 3) v = xr[r * 6 + c];
        else if (c < 63) {
            const int q = c - 3, f = q / 6, rem = q % 6;
            const float ang = xr[r * 6 + (rem % 3)] * (float)(1 << f);
            v = (rem < 3) ? sinf(ang) : cosf(ang);
        }
        sX[r * XSTH + c] = __float2half_rn(v);
    }
    for (int idx = tid; idx < TILE * 64; idx += BLK) {
        const int r = idx >> 6, c = idx & 63;
        float v = 0.0f;
        if (c < 3) v = xr[r * 6 + 3 + c];
        else if (c < 27) {
            const int q = c - 3, f = q / 6, rem = q % 6;
            const float ang = xr[r * 6 + 3 + (rem % 3)] * (float)(1 << f);
            v = (rem < 3) ? sinf(ang) : cosf(ang);
        }
        sDr[r * DSTH + c] = __float2half_rn(v);
    }
    __syncthreads();

    const __half* wsegs[8] = { g_wh + SEG1, g_wh + SEG2, g_wh + SEG3,
                               g_wh + SEG4H, g_wh + SEG5, g_wh + SEG6,
                               g_wh + SEG7, g_wh + SEGF };

    // ---- layers 0..7 (relu) + final (no relu) ----
    float acc[2][4][4];
    for (int L = 0; L <= 8; ++L) {
        const float* B = (L < 8) ? p.b[L] : p.bf;

        if (L == 8) {
            // sigma from layer-7 h (before overwrite)
            __syncthreads();
            if (tid < 256) {
                const int r = tid >> 2, q = tid & 3;
                const __half* hr = sH + r * HSTH + q * 64;
                const float* ws = p.ws + q * 64;
                float s = 0.0f;
#pragma unroll 8
                for (int i = 0; i < 64; ++i)
                    s = fmaf(__half2float(hr[i]), __ldg(ws + i), s);
                s += __shfl_xor_sync(0xffffffffu, s, 1);
                s += __shfl_xor_sync(0xffffffffu, s, 2);
                if (q == 0) sSig[r] = s + __ldg(p.bs);
            }
            __syncthreads();
        }

        zero_acc(acc);
        if (L == 0) {
            gemm_async<256>(acc, sX, XSTH, g_wh + SEG0, 64,
                            sW0, sW1, sW2, tid, wid, lane, true);
        } else {
            if (L == 4)
                gemm_async<256>(acc, sX, XSTH, g_wh + SEG4X, 64,
                                sW0, sW1, sW2, tid, wid, lane, true);
            gemm_async<256>(acc, sH, HSTH, wsegs[L - 1], 256,
                            sW0, sW1, sW2, tid, wid, lane, true);
        }
        epilogue(acc, sH, HSTH, B, /*relu=*/(L < 8), wid, lane);
    }

    // ---- rgb1: relu([final(256) | dir(27 pad 64)] @ w_rgb1 + b_rgb1) ----
    const bool act1 = (wid < 8);
    zero_acc(acc);
    gemm_async<128>(acc, sH,  HSTH, g_wh + SEGR1, 256,
                    sW0, sW1, sW2, tid, wid, lane, act1);
    gemm_async<128>(acc, sDr, DSTH, g_wh + SEGR1D, 64,
                    sW0, sW1, sW2, tid, wid, lane, act1);
    if (act1) epilogue(acc, sHid, HIDH, p.br1, true, wid, lane);
    __syncthreads();

    // ---- rgb2 + sigmoid + output [N,4] = [rgb, sigma] ----
    if (tid < 192) {
        const int r = tid / 3, c = tid % 3;
        float s = __ldg(p.br2 + c);
        const __half* hr = sHid + r * HIDH;
#pragma unroll 8
        for (int k = 0; k < 128; ++k)
            s = fmaf(__half2float(hr[k]), __ldg(p.wr2 + k * 3 + c), s);
        p.out[(p0 + r) * 4 + c] = 1.0f / (1.0f + expf(-s));
    } else if (tid < 256) {
        const int r = tid - 192;
        p.out[(p0 + r) * 4 + 3] = sSig[r];
    }
}

extern "C" void kernel_launch(void* const* d_in, const int* in_sizes, int n_in,
                              void* d_out, int out_size) {
    Params p;
    p.x = (const float*)d_in[0];
    const float* w[8];
    for (int i = 0; i < 8; ++i) {
        w[i]   = (const float*)d_in[1 + 2 * i];
        p.b[i] = (const float*)d_in[2 + 2 * i];
    }
    const float* wf  = (const float*)d_in[17];
    p.bf  = (const float*)d_in[18];
    p.ws  = (const float*)d_in[19];
    p.bs  = (const float*)d_in[20];
    const float* wr1 = (const float*)d_in[21];
    p.br1 = (const float*)d_in[22];
    p.wr2 = (const float*)d_in[23];
    p.br2 = (const float*)d_in[24];
    p.out = (float*)d_out;

    ConvParams cp;
    cp.s[0]  = { w[0],            63, 256, SEG0,   16384 };
    cp.s[1]  = { w[1],           256, 256, SEG1,   65536 };
    cp.s[2]  = { w[2],           256, 256, SEG2,   65536 };
    cp.s[3]  = { w[3],           256, 256, SEG3,   65536 };
    cp.s[4]  = { w[4],            63, 256, SEG4X,  16384 };
    cp.s[5]  = { w[4] + 63 * 256, 256, 256, SEG4H, 65536 };
    cp.s[6]  = { w[5],           256, 256, SEG5,   65536 };
    cp.s[7]  = { w[6],           256, 256, SEG6,   65536 };
    cp.s[8]  = { w[7],           256, 256, SEG7,   65536 };
    cp.s[9]  = { wf,             256, 256, SEGF,   65536 };
    cp.s[10] = { wr1,            256, 128, SEGR1,  32768 };
    cp.s[11] = { wr1 + 256*128,   27, 128, SEGR1D,  8192 };

    conv_weights<<<(WH_TOTAL + 511) / 512, 512>>>(cp);

    cudaFuncSetAttribute((const void*)nerf_fused,
                         cudaFuncAttributeMaxDynamicSharedMemorySize, SMEM_BYTES);

    const int npts    = in_sizes[0] / 6;
    const int nblocks = npts / TILE;
    nerf_fused<<<nblocks, BLK, SMEM_BYTES>>>(p);
}

// round 13
// speedup vs baseline: 4.4262x; 1.0849x over previous
#include <cuda_runtime.h>
#include <cuda_fp16.h>

// Fused NeRF MLP forward, fp16 mma.sync.m16n8k16, fp32 accum.
// 128 points/CTA, 512 threads (16 warps = 4 Mgrp x 4 Ngrp), warp tile 32x32.
// Each layer = two N-half passes over staged weights (halves L2 weight traffic
// per point vs 64-pt CTAs). Activations ping-pong in smem (fp16).

#define MTILE 128
#define BLK   512

// strides in halves (row stride bytes % 128 == 16 -> conflict-free ldmatrix)
#define HSTH  264
#define XSTH  72
#define DSTH  72
#define HIDH  136

// ---- packed fp16 weight buffer (halves), layout [(k/2)][N][2] per segment ----
#define SEG0   0        // L0 xyz     64 x 256
#define SEG1   16384
#define SEG2   81920
#define SEG3   147456
#define SEG4X  212992   // L4 xyz     64 x 256
#define SEG4H  229376
#define SEG5   294912
#define SEG6   360448
#define SEG7   425984
#define SEGF   491520
#define SEGR1  557056   // rgb1 h    256 x 128
#define SEGR1D 589824   // rgb1 dir   64 x 128
#define WH_TOTAL 598016
__device__ __align__(16) __half g_wh[WH_TOTAL];

// ---- smem byte offsets ----
#define OFF_H0   0                          // 128*264*2 = 67584
#define OFF_H1   67584                      // 67584
#define OFF_X    135168                     // 128*72*2  = 18432
#define OFF_D    153600                     // 18432
#define OFF_W0   172032                     // 16384 (32 pair-rows x 512B)
#define OFF_W1   188416
#define OFF_W2   204800
#define OFF_SIG  221184                     // 128*4
#define OFF_HID  OFF_X                      // aliases X/D region (34816 B)
#define SMEM_BYTES 221696

struct Params {
    const float* x;
    const float* b[8];
    const float *bf, *ws, *bs, *br1, *wr2, *br2;
    float* out;
};

struct ConvSeg { const float* src; int k_real; int N; int dst_off; int sz; };
struct ConvParams { ConvSeg s[12]; };

__global__ void conv_weights(ConvParams cp) {
    const int idx = blockIdx.x * blockDim.x + threadIdx.x;
    if (idx >= WH_TOTAL) return;
    int si = 0;
#pragma unroll
    for (int i = 1; i < 12; ++i)
        if (idx >= cp.s[i].dst_off) si = i;
    const ConvSeg g = cp.s[si];
    const int local = idx - g.dst_off;
    const int t  = local >> 1;
    const int n  = t % g.N;
    const int pr = t / g.N;
    const int k  = 2 * pr + (local & 1);
    const float v = (k < g.k_real) ? g.src[k * g.N + n] : 0.0f;
    g_wh[idx] = __float2half_rn(v);
}

__device__ __forceinline__ void mma16(float c[4], const unsigned a[4],
                                      unsigned b0, unsigned b1) {
    asm volatile(
        "mma.sync.aligned.m16n8k16.row.col.f32.f16.f16.f32 "
        "{%0,%1,%2,%3}, {%4,%5,%6,%7}, {%8,%9}, {%0,%1,%2,%3};\n"
        : "+f"(c[0]), "+f"(c[1]), "+f"(c[2]), "+f"(c[3])
        : "r"(a[0]), "r"(a[1]), "r"(a[2]), "r"(a[3]), "r"(b0), "r"(b1));
}
__device__ __forceinline__ void ldsm_x4(unsigned r[4], const __half* p) {
    unsigned addr = (unsigned)__cvta_generic_to_shared(p);
    asm volatile("ldmatrix.sync.aligned.m8n8.x4.shared.b16 {%0,%1,%2,%3}, [%4];\n"
        : "=r"(r[0]), "=r"(r[1]), "=r"(r[2]), "=r"(r[3]) : "r"(addr));
}
__device__ __forceinline__ void cpa16(unsigned sdst, const void* g) {
    asm volatile("cp.async.cg.shared.global [%0], [%1], 16;" :: "r"(sdst), "l"(g));
}
#define CPA_COMMIT() asm volatile("cp.async.commit_group;" ::: "memory")
#define CPA_WAIT(n)  asm volatile("cp.async.wait_group %0;" :: "n"(n) : "memory")

// One 64-k chunk of a 128-col pass. sW words: [pair_row 0..31][128],
// column permutation P(j,n) = cb + n*4 + j, chunk swizzle (pr&3)<<1.
__device__ __forceinline__ void mma_chunk4(float acc[2][4][4],
        const __half* __restrict__ sA, int astH, int kbH,
        const float* __restrict__ sW, int mg, int ng, int lane)
{
    const int g    = lane >> 2;
    const int tig  = lane & 3;
    const int mat  = lane >> 3;
    const int arow = ((mat & 1) << 3) + (lane & 7);
    const int akof = (mat >> 1) << 3;
    const int rb   = mg * 32;
    const int c0   = (((ng << 3) + g) ^ (tig << 1)) << 2;

#pragma unroll
    for (int s = 0; s < 4; ++s) {
        unsigned a[2][4];
#pragma unroll
        for (int m = 0; m < 2; ++m) {
            const __half* ap = sA + (rb + 16 * m + arow) * astH
                                  + kbH + 16 * s + akof;
            ldsm_x4(a[m], ap);
        }
        const float* r0p = sW + (8 * s + tig) * 128;
        const float* r1p = r0p + 4 * 128;
        const float4 q0 = *(const float4*)(r0p + c0);
        const float4 q1 = *(const float4*)(r1p + c0);
        const unsigned* b0 = (const unsigned*)&q0;
        const unsigned* b1 = (const unsigned*)&q1;
#pragma unroll
        for (int j = 0; j < 4; ++j) {
            mma16(acc[0][j], a[0], b0[j], b1[j]);
            mma16(acc[1][j], a[1], b0[j], b1[j]);
        }
    }
}

// stage one 64-k chunk (32 pair-rows x 512B) from packed weights.
// pitchH = halves per pair-row in gmem (512 for N=256 segs, 256 for N=128).
__device__ __forceinline__ void stage_w(unsigned dst, const __half* src,
                                        int pitchH, int tid) {
#pragma unroll
    for (int i = 0; i < 2; ++i) {
        const int cl = tid + i * BLK;
        const int pr = cl >> 5;
        const int cs = cl & 31;
        cpa16(dst + pr * 512 + ((cs ^ ((pr & 3) << 1)) << 4),
              src + pr * pitchH + cs * 8);
    }
}

// One accumulation pass: sA[128 x 64*n] @ W[64*n x 128] += acc.
__device__ __forceinline__ void gemm_pass(float acc[2][4][4],
        const __half* __restrict__ sA, int astH,
        const __half* __restrict__ gW, int pitchH, int n,
        const unsigned char* smbase, unsigned sb,
        int tid, int mg, int ng, int lane)
{
    const float* wb[3] = { (const float*)(smbase + OFF_W0),
                           (const float*)(smbase + OFF_W1),
                           (const float*)(smbase + OFF_W2) };
    const unsigned wa[3] = { sb + OFF_W0, sb + OFF_W1, sb + OFF_W2 };
    stage_w(wa[0], gW, pitchH, tid);
    CPA_COMMIT();
    if (n > 1) { stage_w(wa[1], gW + 32 * pitchH, pitchH, tid); CPA_COMMIT(); }
    for (int c = 0; c < n; ++c) {
        if (c + 1 < n) CPA_WAIT(1); else CPA_WAIT(0);
        __syncthreads();
        mma_chunk4(acc, sA, astH, c * 64, wb[c % 3], mg, ng, lane);
        if (c + 2 < n) {
            stage_w(wa[(c + 2) % 3], gW + (c + 2) * 32 * pitchH, pitchH, tid);
            CPA_COMMIT();
        }
    }
    __syncthreads();
}

// epilogue: 8 contiguous cols per thread-row -> one STS.128 per row.
__device__ __forceinline__ void epi(float acc[2][4][4],
        __half* __restrict__ sDst, int dstH,
        const float* __restrict__ gB, int cb,
        bool relu, int mg, int lane)
{
    const int g   = lane >> 2;
    const int tig = lane & 3;
    const int rb  = mg * 32;
    const int cbase = cb + 8 * tig;
    const float4 bA = *(const float4*)(gB + cbase);
    const float4 bB = *(const float4*)(gB + cbase + 4);
    const float bias[8] = { bA.x, bA.y, bA.z, bA.w, bB.x, bB.y, bB.z, bB.w };
#pragma unroll
    for (int m = 0; m < 2; ++m) {
#pragma unroll
        for (int h = 0; h < 2; ++h) {
            const int row = rb + 16 * m + 8 * h + g;
            __half hv[8];
#pragma unroll
            for (int j = 0; j < 4; ++j) {
                float v0 = acc[m][j][2 * h + 0] + bias[j];
                float v1 = acc[m][j][2 * h + 1] + bias[4 + j];
                if (relu) { v0 = fmaxf(v0, 0.0f); v1 = fmaxf(v1, 0.0f); }
                hv[j]     = __float2half_rn(v0);
                hv[4 + j] = __float2half_rn(v1);
            }
            *(uint4*)(sDst + row * dstH + cbase) = *(const uint4*)hv;
        }
    }
}

__device__ __forceinline__ void zacc(float acc[2][4][4]) {
#pragma unroll
    for (int m = 0; m < 2; ++m)
#pragma unroll
        for (int j = 0; j < 4; ++j)
#pragma unroll
            for (int q = 0; q < 4; ++q) acc[m][j][q] = 0.0f;
}

__global__ void __launch_bounds__(BLK, 1) nerf_fused(Params p) {
    extern __shared__ unsigned char sm[];
    const unsigned sb = (unsigned)__cvta_generic_to_shared(sm);
    __half* hbuf0 = (__half*)(sm + OFF_H0);
    __half* hbuf1 = (__half*)(sm + OFF_H1);
    __half* sX    = (__half*)(sm + OFF_X);
    __half* sDr   = (__half*)(sm + OFF_D);
    __half* sHid  = (__half*)(sm + OFF_HID);
    float*  sSig  = (float*) (sm + OFF_SIG);

    const int tid  = threadIdx.x;
    const int wid  = tid >> 5;
    const int lane = tid & 31;
    const int mg   = wid & 3;
    const int ng   = wid >> 2;
    const int p0   = blockIdx.x * MTILE;

    // ---- raw x into weight-buf scratch, then positional encodings ----
    float* xr = (float*)(sm + OFF_W0);
    for (int idx = tid; idx < MTILE * 6; idx += BLK)
        xr[idx] = p.x[p0 * 6 + idx];
    __syncthreads();

    for (int idx = tid; idx < MTILE * 64; idx += BLK) {
        const int r = idx >> 6, c = idx & 63;
        float v = 0.0f;
        if (c < 3) v = xr[r * 6 + c];
        else if (c < 63) {
            const int q = c - 3, f = q / 6, rem = q % 6;
            const float ang = xr[r * 6 + (rem % 3)] * (float)(1 << f);
            v = (rem < 3) ? sinf(ang) : cosf(ang);
        }
        sX[r * XSTH + c] = __float2half_rn(v);
    }
    for (int idx = tid; idx < MTILE * 64; idx += BLK) {
        const int r = idx >> 6, c = idx & 63;
        float v = 0.0f;
        if (c < 3) v = xr[r * 6 + 3 + c];
        else if (c < 27) {
            const int q = c - 3, f = q / 6, rem = q % 6;
            const float ang = xr[r * 6 + 3 + (rem % 3)] * (float)(1 << f);
            v = (rem < 3) ? sinf(ang) : cosf(ang);
        }
        sDr[r * DSTH + c] = __float2half_rn(v);
    }
    __syncthreads();

    const int wseg[8] = { SEG1, SEG2, SEG3, SEG4H, SEG5, SEG6, SEG7, SEGF };

    // ---- layers 0..7 (relu) + final L8 (no relu) ----
    // out(L) = hbuf0 for even L, hbuf1 for odd L
    float acc[2][4][4];
    for (int L = 0; L <= 8; ++L) {
        const float* B = (L < 8) ? p.b[L] : p.bf;
        __half* out = (L & 1) ? hbuf1 : hbuf0;
        __half* in  = (L & 1) ? hbuf0 : hbuf1;
#pragma unroll 1
        for (int nh = 0; nh < 2; ++nh) {
            zacc(acc);
            if (L == 0) {
                gemm_pass(acc, sX, XSTH, g_wh + SEG0 + nh * 256, 512, 1,
                          sm, sb, tid, mg, ng, lane);
            } else {
                if (L == 4)
                    gemm_pass(acc, sX, XSTH, g_wh + SEG4X + nh * 256, 512, 1,
                              sm, sb, tid, mg, ng, lane);
                gemm_pass(acc, in, HSTH, g_wh + wseg[L - 1] + nh * 256, 512, 4,
                          sm, sb, tid, mg, ng, lane);
            }
            epi(acc, out, HSTH, B, nh * 128 + ng * 32, /*relu=*/(L < 8),
                mg, lane);
        }
    }

    // ---- sigma from h7 (hbuf1; L8 wrote hbuf0) ----
    {
        const int r = tid >> 2, q = tid & 3;
        const __half* hr = hbuf1 + r * HSTH + q * 64;
        const float* ws = p.ws + q * 64;
        float s = 0.0f;
#pragma unroll 8
        for (int i = 0; i < 64; ++i)
            s = fmaf(__half2float(hr[i]), __ldg(ws + i), s);
        s += __shfl_xor_sync(0xffffffffu, s, 1);
        s += __shfl_xor_sync(0xffffffffu, s, 2);
        if (q == 0) sSig[r] = s + __ldg(p.bs);
    }

    // ---- rgb1: relu([final(256) | dir(27 pad 64)] @ w_rgb1 + b_rgb1) ----
    zacc(acc);
    gemm_pass(acc, hbuf0, HSTH, g_wh + SEGR1, 256, 4,
              sm, sb, tid, mg, ng, lane);
    gemm_pass(acc, sDr, DSTH, g_wh + SEGR1D, 256, 1,
              sm, sb, tid, mg, ng, lane);
    epi(acc, sHid, HIDH, p.br1, ng * 32, true, mg, lane);
    __syncthreads();

    // ---- rgb2 + sigmoid + output [N,4] = [rgb, sigma] ----
    if (tid < 384) {
        const int r = tid / 3, c = tid % 3;
        float s = __ldg(p.br2 + c);
        const __half* hr = sHid + r * HIDH;
#pragma unroll 8
        for (int k = 0; k < 128; ++k)
            s = fmaf(__half2float(hr[k]), __ldg(p.wr2 + k * 3 + c), s);
        p.out[(p0 + r) * 4 + c] = 1.0f / (1.0f + expf(-s));
    } else {
        const int r = tid - 384;
        p.out[(p0 + r) * 4 + 3] = sSig[r];
    }
}

extern "C" void kernel_launch(void* const* d_in, const int* in_sizes, int n_in,
                              void* d_out, int out_size) {
    Params p;
    p.x = (const float*)d_in[0];
    const float* w[8];
    for (int i = 0; i < 8; ++i) {
        w[i]   = (const float*)d_in[1 + 2 * i];
        p.b[i] = (const float*)d_in[2 + 2 * i];
    }
    const float* wf  = (const float*)d_in[17];
    p.bf  = (const float*)d_in[18];
    p.ws  = (const float*)d_in[19];
    p.bs  = (const float*)d_in[20];
    const float* wr1 = (const float*)d_in[21];
    p.br1 = (const float*)d_in[22];
    p.wr2 = (const float*)d_in[23];
    p.br2 = (const float*)d_in[24];
    p.out = (float*)d_out;

    ConvParams cp;
    cp.s[0]  = { w[0],            63, 256, SEG0,   16384 };
    cp.s[1]  = { w[1],           256, 256, SEG1,   65536 };
    cp.s[2]  = { w[2],           256, 256, SEG2,   65536 };
    cp.s[3]  = { w[3],           256, 256, SEG3,   65536 };
    cp.s[4]  = { w[4],            63, 256, SEG4X,  16384 };
    cp.s[5]  = { w[4] + 63 * 256, 256, 256, SEG4H, 65536 };
    cp.s[6]  = { w[5],           256, 256, SEG5,   65536 };
    cp.s[7]  = { w[6],           256, 256, SEG6,   65536 };
    cp.s[8]  = { w[7],           256, 256, SEG7,   65536 };
    cp.s[9]  = { wf,             256, 256, SEGF,   65536 };
    cp.s[10] = { wr1,            256, 128, SEGR1,  32768 };
    cp.s[11] = { wr1 + 256*128,   27, 128, SEGR1D,  8192 };

    conv_weights<<<(WH_TOTAL + 511) / 512, 512>>>(cp);

    cudaFuncSetAttribute((const void*)nerf_fused,
                         cudaFuncAttributeMaxDynamicSharedMemorySize, SMEM_BYTES);

    const int npts    = in_sizes[0] / 6;
    const int nblocks = npts / MTILE;
    nerf_fused<<<nblocks, BLK, SMEM_BYTES>>>(p);
}